// round 2
// baseline (speedup 1.0000x reference)
#include <cuda_runtime.h>
#include <cstdint>
#include <cstddef>

#define BB 32
#define SQ 2048
#define SK 2048
#define DD 64
#define TQ 16          // q rows per CTA
#define KT 256         // k rows per smem tile
#define KSTRIDE 68     // padded row stride (floats) for K/V tile -> conflict-free LDS.128
#define NTHREADS 256

// dynamic smem layout (floats):
//   S  : TQ * SK            = 32768 floats (131072 B)  softmax scratch / P matrix
//   KV : KT * KSTRIDE       = 17408 floats ( 69632 B)  K tile, then V tile, then O partials
//   Qs : TQ * DD            =  1024 floats (  4096 B)
#define SMEM_FLOATS (TQ*SK + KT*KSTRIDE + TQ*DD)
#define SMEM_BYTES  (SMEM_FLOATS * 4)

__global__ void __launch_bounds__(NTHREADS, 1)
sdpa_kernel(const float* __restrict__ Qg,
            const float* __restrict__ Kg,
            const float* __restrict__ Vg,
            const int*   __restrict__ Mg,     // bool mask marshaled as 4-byte words
            float* __restrict__ attn_out,
            float* __restrict__ o_out)
{
    extern __shared__ float smem[];
    float* S  = smem;                 // [TQ][SK]
    float* KV = smem + TQ * SK;       // [KT][KSTRIDE]
    float* Qs = KV + KT * KSTRIDE;    // [TQ][DD]

    const int tid   = threadIdx.x;
    const int b     = blockIdx.y;
    const int qbase = blockIdx.x * TQ;

    // ---------------- Phase 0: load Q tile (scaled by 1/sqrt(64) = 0.125) ----------------
    {
        const float4* qg = (const float4*)(Qg + ((size_t)b * SQ + qbase) * DD);
        for (int v = tid; v < TQ * DD / 4; v += NTHREADS) {
            float4 x = qg[v];
            x.x *= 0.125f; x.y *= 0.125f; x.z *= 0.125f; x.w *= 0.125f;
            *(float4*)&Qs[v * 4] = x;   // row stride DD=64, contiguous
        }
    }

    // ---------------- Phase 1: S = (Q*0.125) @ K^T, full row block in smem ----------------
    {
        const int qr = tid >> 6;   // 0..3  -> q rows qr*4 + i
        const int kc = tid & 63;   // 0..63 -> k cols kc + 64*j

        for (int kt = 0; kt < SK / KT; kt++) {
            // load K tile [KT][DD] into KV with padded stride
            const float4* kg = (const float4*)(Kg + ((size_t)b * SK + (size_t)kt * KT) * DD);
            for (int v = tid; v < KT * DD / 4; v += NTHREADS) {
                float4 x = kg[v];
                int row = v >> 4, dch = v & 15;
                *(float4*)&KV[row * KSTRIDE + dch * 4] = x;
            }
            __syncthreads();

            float acc[4][4];
            #pragma unroll
            for (int i = 0; i < 4; i++)
                #pragma unroll
                for (int j = 0; j < 4; j++) acc[i][j] = 0.f;

            #pragma unroll 4
            for (int dc = 0; dc < 16; dc++) {
                float4 qf[4], kf[4];
                #pragma unroll
                for (int i = 0; i < 4; i++)
                    qf[i] = *(const float4*)&Qs[(qr * 4 + i) * DD + dc * 4];
                #pragma unroll
                for (int j = 0; j < 4; j++)
                    kf[j] = *(const float4*)&KV[(kc + 64 * j) * KSTRIDE + dc * 4];
                #pragma unroll
                for (int i = 0; i < 4; i++)
                    #pragma unroll
                    for (int j = 0; j < 4; j++) {
                        acc[i][j] += qf[i].x * kf[j].x;
                        acc[i][j] += qf[i].y * kf[j].y;
                        acc[i][j] += qf[i].z * kf[j].z;
                        acc[i][j] += qf[i].w * kf[j].w;
                    }
            }

            #pragma unroll
            for (int i = 0; i < 4; i++)
                #pragma unroll
                for (int j = 0; j < 4; j++)
                    S[(qr * 4 + i) * SK + kt * KT + kc + 64 * j] = acc[i][j];

            __syncthreads();   // protect KV before next tile load
        }
    }

    // ---------------- Phase 2: masked softmax per row; write attn, keep P in smem ----------
    {
        const int warpid = tid >> 5;
        const int lane   = tid & 31;
        for (int rr = 0; rr < 2; rr++) {
            const int q = warpid * 2 + rr;
            const int4* mrow = (const int4*)(Mg + ((size_t)b * SQ + qbase + q) * SK);
            float4* Srow = (float4*)&S[q * SK];

            // pass A: masked max
            float m = -1e9f;
            #pragma unroll 4
            for (int j = lane; j < SK / 4; j += 32) {
                int4  mk = mrow[j];
                float4 s = Srow[j];
                float v0 = mk.x ? s.x : -1e9f;
                float v1 = mk.y ? s.y : -1e9f;
                float v2 = mk.z ? s.z : -1e9f;
                float v3 = mk.w ? s.w : -1e9f;
                m = fmaxf(m, fmaxf(fmaxf(v0, v1), fmaxf(v2, v3)));
            }
            #pragma unroll
            for (int o = 16; o; o >>= 1) m = fmaxf(m, __shfl_xor_sync(0xffffffffu, m, o));

            // pass B: exp, row sum; stash exp back into S
            float sum = 0.f;
            #pragma unroll 4
            for (int j = lane; j < SK / 4; j += 32) {
                int4  mk = mrow[j];
                float4 s = Srow[j];
                float4 e;
                e.x = __expf((mk.x ? s.x : -1e9f) - m);
                e.y = __expf((mk.y ? s.y : -1e9f) - m);
                e.z = __expf((mk.z ? s.z : -1e9f) - m);
                e.w = __expf((mk.w ? s.w : -1e9f) - m);
                sum += e.x + e.y + e.z + e.w;
                Srow[j] = e;
            }
            #pragma unroll
            for (int o = 16; o; o >>= 1) sum += __shfl_xor_sync(0xffffffffu, sum, o);
            const float inv = 1.0f / sum;

            // pass C: normalize, write attn row (coalesced float4), keep P in smem
            float4* arow = (float4*)(attn_out + ((size_t)b * SQ + qbase + q) * SK);
            #pragma unroll 4
            for (int j = lane; j < SK / 4; j += 32) {
                float4 e = Srow[j];
                e.x *= inv; e.y *= inv; e.z *= inv; e.w *= inv;
                Srow[j] = e;
                arow[j] = e;
            }
        }
        __syncthreads();
    }

    // ---------------- Phase 3: O = P @ V, split-K across two 128-thread groups -------------
    {
        const int g   = tid >> 7;   // 0/1: k-halves of each V tile
        const int t   = tid & 127;
        const int pqr = t >> 5;     // 0..3 -> q rows pqr*4 + i
        const int dc  = t & 31;     // 0..31 -> d cols dc*2 + {0,1}

        float acc[4][2];
        #pragma unroll
        for (int i = 0; i < 4; i++) { acc[i][0] = 0.f; acc[i][1] = 0.f; }

        for (int vt = 0; vt < SK / KT; vt++) {
            __syncthreads();
            const float4* vg = (const float4*)(Vg + ((size_t)b * SK + (size_t)vt * KT) * DD);
            for (int v = tid; v < KT * DD / 4; v += NTHREADS) {
                float4 x = vg[v];
                int row = v >> 4, dch = v & 15;
                *(float4*)&KV[row * KSTRIDE + dch * 4] = x;
            }
            __syncthreads();

            const int kbase = vt * KT + g * 128;
            #pragma unroll 4
            for (int kk = 0; kk < 128; kk += 4) {
                float4 pf[4];
                #pragma unroll
                for (int i = 0; i < 4; i++)
                    pf[i] = *(const float4*)&S[(pqr * 4 + i) * SK + kbase + kk];
                float2 vf[4];
                #pragma unroll
                for (int u = 0; u < 4; u++)
                    vf[u] = *(const float2*)&KV[(g * 128 + kk + u) * KSTRIDE + dc * 2];
                #pragma unroll
                for (int i = 0; i < 4; i++) {
                    acc[i][0] += pf[i].x * vf[0].x; acc[i][1] += pf[i].x * vf[0].y;
                    acc[i][0] += pf[i].y * vf[1].x; acc[i][1] += pf[i].y * vf[1].y;
                    acc[i][0] += pf[i].z * vf[2].x; acc[i][1] += pf[i].z * vf[2].y;
                    acc[i][0] += pf[i].w * vf[3].x; acc[i][1] += pf[i].w * vf[3].y;
                }
            }
        }

        __syncthreads();            // everyone done reading KV as V tile
        float* Op = KV;             // reuse: [2][TQ][DD] partials
        #pragma unroll
        for (int i = 0; i < 4; i++) {
            float2 w; w.x = acc[i][0]; w.y = acc[i][1];
            *(float2*)&Op[((size_t)g * TQ + pqr * 4 + i) * DD + dc * 2] = w;
        }
        __syncthreads();

        float4* orow = (float4*)(o_out + ((size_t)b * SQ + qbase) * DD);
        const float4* p0 = (const float4*)Op;
        const float4* p1 = (const float4*)(Op + TQ * DD);
        for (int v = tid; v < TQ * DD / 4; v += NTHREADS) {
            float4 a = p0[v], c = p1[v];
            a.x += c.x; a.y += c.y; a.z += c.z; a.w += c.w;
            orow[v] = a;
        }
    }
}

extern "C" void kernel_launch(void* const* d_in, const int* in_sizes, int n_in,
                              void* d_out, int out_size)
{
    const float* Q    = (const float*)d_in[0];
    const float* K    = (const float*)d_in[1];
    const float* V    = (const float*)d_in[2];
    const int*   mask = (const int*)d_in[3];   // bool marshaled as 4-byte words

    float* attn = (float*)d_out;                                   // [B, SQ, SK]
    float* outp = attn + (size_t)BB * SQ * SK;                     // [B, SQ, D]

    cudaFuncSetAttribute(sdpa_kernel,
                         cudaFuncAttributeMaxDynamicSharedMemorySize, SMEM_BYTES);

    dim3 grid(SQ / TQ, BB);
    sdpa_kernel<<<grid, NTHREADS, SMEM_BYTES>>>(Q, K, V, mask, attn, outp);
}